// round 11
// baseline (speedup 1.0000x reference)
#include <cuda_runtime.h>
#include <cuda_bf16.h>
#include <math.h>

// ---------------- problem constants ----------------
#define NN 20000          // nodes
#define NE 640000         // edges (before self-loops)
#define NET (NE + NN)     // edges with self-loops
#define NG 64             // graphs
#define FIN 128
#define C1 64             // per-head channels layer1 (2 heads -> 128)
#define H1 2
#define HC1 (H1 * C1)     // 128
#define C2 64
#define HC2 64
#define CLSH 64
#define NEG_SLOPE 0.2f

// ---------------- device scratch (referenced directly by symbol in kernels) ----------------
__device__ float g_xh1[NN * HC1];
__device__ float g_h1[NN * HC1];
__device__ float g_xh2[NN * HC2];
__device__ float g_h2[NN * HC2];
__device__ float g_als1[NN * H1];
__device__ float g_ald1[NN * H1];
__device__ float g_z1[NN * H1];
__device__ float g_als2[NN];
__device__ float g_ald2[NN];
__device__ float g_z2[NN];
__device__ float g_ew1[(size_t)NET * H1];
__device__ float g_ew2[(size_t)NET];

// ---------------- kernels ----------------

// zero all per-call accumulators (z1, z2, h1, h2) in one kernel
__global__ void zero_scratch_kernel() {
    int i = blockIdx.x * blockDim.x + threadIdx.x;
    if (i < NN * HC1) g_h1[i] = 0.0f;
    if (i < NN * HC2) g_h2[i] = 0.0f;
    if (i < NN * H1)  g_z1[i] = 0.0f;
    if (i < NN)       g_z2[i] = 0.0f;
}

// C[M,N] = A[M,K] @ B[K,N].  BM=BN=64, BK=16, 16x16 threads, 4x4 per thread.
__device__ __forceinline__ void gemm_body(const float* __restrict__ A, const float* __restrict__ B,
                                          float* __restrict__ C, int M, int N, int K) {
    __shared__ float As[64][17];
    __shared__ float Bs[16][64];
    int block_row = blockIdx.y * 64;
    int block_col = blockIdx.x * 64;
    int tx = threadIdx.x, ty = threadIdx.y;
    int tid = ty * 16 + tx;
    float acc[4][4] = {};
    for (int k0 = 0; k0 < K; k0 += 16) {
        for (int i = tid; i < 64 * 16; i += 256) {
            int r = i >> 4, c = i & 15;
            int gr = block_row + r;
            As[r][c] = (gr < M) ? A[(size_t)gr * K + k0 + c] : 0.0f;
        }
        for (int i = tid; i < 16 * 64; i += 256) {
            int r = i >> 6, c = i & 63;
            Bs[r][c] = B[(size_t)(k0 + r) * N + block_col + c];
        }
        __syncthreads();
#pragma unroll
        for (int kk = 0; kk < 16; kk++) {
            float a[4], b[4];
#pragma unroll
            for (int i = 0; i < 4; i++) a[i] = As[ty * 4 + i][kk];
#pragma unroll
            for (int j = 0; j < 4; j++) b[j] = Bs[kk][tx * 4 + j];
#pragma unroll
            for (int i = 0; i < 4; i++)
#pragma unroll
                for (int j = 0; j < 4; j++) acc[i][j] += a[i] * b[j];
        }
        __syncthreads();
    }
#pragma unroll
    for (int i = 0; i < 4; i++) {
        int gr = block_row + ty * 4 + i;
        if (gr < M) {
#pragma unroll
            for (int j = 0; j < 4; j++)
                C[(size_t)gr * N + block_col + tx * 4 + j] = acc[i][j];
        }
    }
}

__global__ void gemm1_kernel(const float* __restrict__ A, const float* __restrict__ B) {
    gemm_body(A, B, g_xh1, NN, HC1, FIN);
}
__global__ void gemm2_kernel(const float* __restrict__ B) {
    gemm_body(g_h1, B, g_xh2, NN, HC2, HC1);
}

// per-(node,head) attention logit halves
__global__ void al1_kernel(const float* __restrict__ a_src, const float* __restrict__ a_dst) {
    int warp = (blockIdx.x * blockDim.x + threadIdx.x) >> 5;  // warp = n*H1 + h
    int lane = threadIdx.x & 31;
    if (warp >= NN * H1) return;
    int h = warp & 1;
    const float* row = g_xh1 + (size_t)warp * C1;
    float s = 0.f, d = 0.f;
    for (int c = lane; c < C1; c += 32) {
        float v = row[c];
        s += v * a_src[h * C1 + c];
        d += v * a_dst[h * C1 + c];
    }
#pragma unroll
    for (int o = 16; o; o >>= 1) {
        s += __shfl_down_sync(0xffffffffu, s, o);
        d += __shfl_down_sync(0xffffffffu, d, o);
    }
    if (lane == 0) { g_als1[warp] = s; g_ald1[warp] = d; }
}

__global__ void al2_kernel(const float* __restrict__ a_src, const float* __restrict__ a_dst) {
    int warp = (blockIdx.x * blockDim.x + threadIdx.x) >> 5;
    int lane = threadIdx.x & 31;
    if (warp >= NN) return;
    const float* row = g_xh2 + (size_t)warp * C2;
    float s = 0.f, d = 0.f;
    for (int c = lane; c < C2; c += 32) {
        float v = row[c];
        s += v * a_src[c];
        d += v * a_dst[c];
    }
#pragma unroll
    for (int o = 16; o; o >>= 1) {
        s += __shfl_down_sync(0xffffffffu, s, o);
        d += __shfl_down_sync(0xffffffffu, d, o);
    }
    if (lane == 0) { g_als2[warp] = s; g_ald2[warp] = d; }
}

// per-edge w = exp(leaky_relu(als[src]+ald[dst])); accumulate z[dst].
// No max-subtraction: alpha = e^x / sum e^x is shift-invariant and |x| is small.
__global__ void edge_w1_kernel(const int* __restrict__ ei) {
    int e = blockIdx.x * blockDim.x + threadIdx.x;
    if (e >= NET) return;
    int s, d;
    if (e < NE) { s = ei[e]; d = ei[NE + e]; }
    else        { s = d = e - NE; }
#pragma unroll
    for (int h = 0; h < H1; h++) {
        float v = g_als1[s * H1 + h] + g_ald1[d * H1 + h];
        v = (v > 0.f) ? v : NEG_SLOPE * v;
        float w = __expf(v);
        g_ew1[(size_t)e * H1 + h] = w;
        atomicAdd(&g_z1[d * H1 + h], w);
    }
}

__global__ void edge_w2_kernel(const int* __restrict__ ei) {
    int e = blockIdx.x * blockDim.x + threadIdx.x;
    if (e >= NET) return;
    int s, d;
    if (e < NE) { s = ei[e]; d = ei[NE + e]; }
    else        { s = d = e - NE; }
    float v = g_als2[s] + g_ald2[d];
    v = (v > 0.f) ? v : NEG_SLOPE * v;
    float w = __expf(v);
    g_ew2[e] = w;
    atomicAdd(&g_z2[d], w);
}

// warp-per-edge scatter: h1[dst, :] += alpha_h * xh1[src, :]   (128 channels, 2 heads)
__global__ void edge_agg1_kernel(const int* __restrict__ ei) {
    int warp = (blockIdx.x * blockDim.x + threadIdx.x) >> 5;
    int lane = threadIdx.x & 31;
    if (warp >= NET) return;
    int s, d;
    if (warp < NE) { s = ei[warp]; d = ei[NE + warp]; }
    else           { s = d = warp - NE; }
    float alpha0 = g_ew1[(size_t)warp * H1]     / g_z1[d * H1];
    float alpha1 = g_ew1[(size_t)warp * H1 + 1] / g_z1[d * H1 + 1];
    const float* src_row = g_xh1 + (size_t)s * HC1;
    float* dst_row = g_h1 + (size_t)d * HC1;
#pragma unroll
    for (int k = 0; k < 4; k++) {
        int c = k * 32 + lane;
        float a = (c < C1) ? alpha0 : alpha1;
        atomicAdd(&dst_row[c], a * src_row[c]);
    }
}

// warp-per-edge scatter: h2[dst, :] += alpha * xh2[src, :]   (64 channels)
__global__ void edge_agg2_kernel(const int* __restrict__ ei) {
    int warp = (blockIdx.x * blockDim.x + threadIdx.x) >> 5;
    int lane = threadIdx.x & 31;
    if (warp >= NET) return;
    int s, d;
    if (warp < NE) { s = ei[warp]; d = ei[NE + warp]; }
    else           { s = d = warp - NE; }
    float alpha = g_ew2[warp] / g_z2[d];
    const float* src_row = g_xh2 + (size_t)s * HC2;
    float* dst_row = g_h2 + (size_t)d * HC2;
#pragma unroll
    for (int k = 0; k < 2; k++) {
        int c = k * 32 + lane;
        atomicAdd(&dst_row[c], alpha * src_row[c]);
    }
}

__global__ void bias_relu1_kernel(const float* __restrict__ b) {
    int i = blockIdx.x * blockDim.x + threadIdx.x;
    if (i >= NN * HC1) return;
    float v = g_h1[i] + b[i & (HC1 - 1)];
    g_h1[i] = fmaxf(v, 0.0f);
}

__global__ void bias2_kernel(const float* __restrict__ b) {
    int i = blockIdx.x * blockDim.x + threadIdx.x;
    if (i >= NN * HC2) return;
    g_h2[i] = g_h2[i] + b[i & (HC2 - 1)];
}

__global__ void pool_zero_kernel(float* __restrict__ out) {
    int i = blockIdx.x * blockDim.x + threadIdx.x;
    if (i < NG * HC2) out[i] = 0.0f;
}

__global__ void pool_kernel(const int* __restrict__ batch, float* __restrict__ ge) {
    int i = blockIdx.x * blockDim.x + threadIdx.x;
    if (i >= NN * HC2) return;
    int n = i >> 6, c = i & 63;
    atomicAdd(&ge[batch[n] * HC2 + c], g_h2[i]);
}

// single block, 64 threads: MLP head + log-softmax + loss + correct count
__global__ void classifier_kernel(const float* __restrict__ Wc1, const float* __restrict__ bc1,
                                  const float* __restrict__ Wc2, const float* __restrict__ bc2,
                                  const int* __restrict__ y,
                                  float* __restrict__ out) {
    int g = threadIdx.x;  // 0..63
    const float* ge = out;  // graph embedding at out[0..NG*HC2)
    __shared__ float loss_sh[NG];
    __shared__ int corr_sh[NG];
    float l0 = bc2[0], l1 = bc2[1];
    for (int j = 0; j < CLSH; j++) {
        float h = bc1[j];
        for (int k = 0; k < HC2; k++) h += ge[g * HC2 + k] * Wc1[k * CLSH + j];
        h = fmaxf(h, 0.0f);
        l0 += h * Wc2[j * 2];
        l1 += h * Wc2[j * 2 + 1];
    }
    float m = fmaxf(l0, l1);
    float e0 = expf(l0 - m), e1 = expf(l1 - m);
    float lse = m + logf(e0 + e1);
    float lp0 = l0 - lse, lp1 = l1 - lse;
    float p0 = expf(lp0), p1 = expf(lp1);
    int yv = y[g];
    loss_sh[g] = -((yv == 0) ? lp0 : lp1);
    corr_sh[g] = (((p1 > p0) ? 1 : 0) == yv) ? 1 : 0;
    out[NG * HC2 + 2 + g * 2]     = p0;
    out[NG * HC2 + 2 + g * 2 + 1] = p1;
    __syncthreads();
    if (g == 0) {
        float L = 0.f; int cc = 0;
        for (int i = 0; i < NG; i++) { L += loss_sh[i]; cc += corr_sh[i]; }
        out[NG * HC2]     = L / (float)NG;
        out[NG * HC2 + 1] = (float)cc;
    }
}

// ---------------- launch ----------------
static inline int cdiv(int a, int b) { return (a + b - 1) / b; }

extern "C" void kernel_launch(void* const* d_in, const int* in_sizes, int n_in,
                              void* d_out, int out_size) {
    const float* x     = (const float*)d_in[0];
    const int*   ei    = (const int*)d_in[1];     // int32 (JAX x64 disabled)
    const int*   batch = (const int*)d_in[2];
    const int*   y     = (const int*)d_in[3];
    const float* W1    = (const float*)d_in[4];
    const float* asrc1 = (const float*)d_in[5];
    const float* adst1 = (const float*)d_in[6];
    const float* b1    = (const float*)d_in[7];
    const float* W2    = (const float*)d_in[8];
    const float* asrc2 = (const float*)d_in[9];
    const float* adst2 = (const float*)d_in[10];
    const float* b2    = (const float*)d_in[11];
    const float* Wc1   = (const float*)d_in[12];
    const float* bc1   = (const float*)d_in[13];
    const float* Wc2   = (const float*)d_in[14];
    const float* bc2   = (const float*)d_in[15];
    float* out = (float*)d_out;

    dim3 t16(16, 16);

    zero_scratch_kernel<<<cdiv(NN * HC1, 256), 256>>>();

    // ---- layer 1 ----
    gemm1_kernel<<<dim3(HC1 / 64, cdiv(NN, 64)), t16>>>(x, W1);
    al1_kernel<<<cdiv(NN * H1 * 32, 256), 256>>>(asrc1, adst1);
    edge_w1_kernel<<<cdiv(NET, 256), 256>>>(ei);
    edge_agg1_kernel<<<cdiv(NET * 32, 256), 256>>>(ei);
    bias_relu1_kernel<<<cdiv(NN * HC1, 256), 256>>>(b1);

    // ---- layer 2 ----
    gemm2_kernel<<<dim3(HC2 / 64, cdiv(NN, 64)), t16>>>(W2);
    al2_kernel<<<cdiv(NN * 32, 256), 256>>>(asrc2, adst2);
    edge_w2_kernel<<<cdiv(NET, 256), 256>>>(ei);
    edge_agg2_kernel<<<cdiv(NET * 32, 256), 256>>>(ei);
    bias2_kernel<<<cdiv(NN * HC2, 256), 256>>>(b2);

    // ---- pool + classifier ----
    pool_zero_kernel<<<cdiv(NG * HC2, 256), 256>>>(out);
    pool_kernel<<<cdiv(NN * HC2, 256), 256>>>(batch, out);
    classifier_kernel<<<1, NG>>>(Wc1, bc1, Wc2, bc2, y, out);
}

// round 12
// speedup vs baseline: 1.0029x; 1.0029x over previous
#include <cuda_runtime.h>
#include <cuda_bf16.h>
#include <math.h>

// ---------------- problem constants ----------------
#define NN 20000          // nodes
#define NE 640000         // edges (before self-loops)
#define NET (NE + NN)     // edges with self-loops
#define NG 64             // graphs
#define FIN 128
#define C1 64             // per-head channels layer1 (2 heads -> 128)
#define H1 2
#define HC1 (H1 * C1)     // 128
#define C2 64
#define HC2 64
#define CLSH 64
#define NEG_SLOPE 0.2f

// ---------------- device scratch (referenced directly by symbol in kernels) ----------------
__device__ float g_xh1[NN * HC1];
__device__ float g_h1[NN * HC1];
__device__ float g_xh2[NN * HC2];
__device__ float g_h2[NN * HC2];
__device__ float g_als1[NN * H1];
__device__ float g_ald1[NN * H1];
__device__ float g_z1[NN * H1];
__device__ float g_als2[NN];
__device__ float g_ald2[NN];
__device__ float g_z2[NN];
__device__ float g_ew1[(size_t)NET * H1];
__device__ float g_ew2[(size_t)NET];

// ---------------- kernels ----------------

// zero all per-call accumulators (z1, z2, h1, h2) in one kernel
__global__ void zero_scratch_kernel() {
    int i = blockIdx.x * blockDim.x + threadIdx.x;
    if (i < NN * HC1) g_h1[i] = 0.0f;
    if (i < NN * HC2) g_h2[i] = 0.0f;
    if (i < NN * H1)  g_z1[i] = 0.0f;
    if (i < NN)       g_z2[i] = 0.0f;
}

// C[M,N] = A[M,K] @ B[K,N].  BM=BN=64, BK=16, 16x16 threads, 4x4 per thread.
__device__ __forceinline__ void gemm_body(const float* __restrict__ A, const float* __restrict__ B,
                                          float* __restrict__ C, int M, int N, int K) {
    __shared__ float As[64][17];
    __shared__ float Bs[16][64];
    int block_row = blockIdx.y * 64;
    int block_col = blockIdx.x * 64;
    int tx = threadIdx.x, ty = threadIdx.y;
    int tid = ty * 16 + tx;
    float acc[4][4] = {};
    for (int k0 = 0; k0 < K; k0 += 16) {
        for (int i = tid; i < 64 * 16; i += 256) {
            int r = i >> 4, c = i & 15;
            int gr = block_row + r;
            As[r][c] = (gr < M) ? A[(size_t)gr * K + k0 + c] : 0.0f;
        }
        for (int i = tid; i < 16 * 64; i += 256) {
            int r = i >> 6, c = i & 63;
            Bs[r][c] = B[(size_t)(k0 + r) * N + block_col + c];
        }
        __syncthreads();
#pragma unroll
        for (int kk = 0; kk < 16; kk++) {
            float a[4], b[4];
#pragma unroll
            for (int i = 0; i < 4; i++) a[i] = As[ty * 4 + i][kk];
#pragma unroll
            for (int j = 0; j < 4; j++) b[j] = Bs[kk][tx * 4 + j];
#pragma unroll
            for (int i = 0; i < 4; i++)
#pragma unroll
                for (int j = 0; j < 4; j++) acc[i][j] += a[i] * b[j];
        }
        __syncthreads();
    }
#pragma unroll
    for (int i = 0; i < 4; i++) {
        int gr = block_row + ty * 4 + i;
        if (gr < M) {
#pragma unroll
            for (int j = 0; j < 4; j++)
                C[(size_t)gr * N + block_col + tx * 4 + j] = acc[i][j];
        }
    }
}

__global__ void gemm1_kernel(const float* __restrict__ A, const float* __restrict__ B) {
    gemm_body(A, B, g_xh1, NN, HC1, FIN);
}
__global__ void gemm2_kernel(const float* __restrict__ B) {
    gemm_body(g_h1, B, g_xh2, NN, HC2, HC1);
}

// per-(node,head) attention logit halves
__global__ void al1_kernel(const float* __restrict__ a_src, const float* __restrict__ a_dst) {
    int warp = (blockIdx.x * blockDim.x + threadIdx.x) >> 5;  // warp = n*H1 + h
    int lane = threadIdx.x & 31;
    if (warp >= NN * H1) return;
    int h = warp & 1;
    const float* row = g_xh1 + (size_t)warp * C1;
    float s = 0.f, d = 0.f;
    for (int c = lane; c < C1; c += 32) {
        float v = row[c];
        s += v * a_src[h * C1 + c];
        d += v * a_dst[h * C1 + c];
    }
#pragma unroll
    for (int o = 16; o; o >>= 1) {
        s += __shfl_down_sync(0xffffffffu, s, o);
        d += __shfl_down_sync(0xffffffffu, d, o);
    }
    if (lane == 0) { g_als1[warp] = s; g_ald1[warp] = d; }
}

__global__ void al2_kernel(const float* __restrict__ a_src, const float* __restrict__ a_dst) {
    int warp = (blockIdx.x * blockDim.x + threadIdx.x) >> 5;
    int lane = threadIdx.x & 31;
    if (warp >= NN) return;
    const float* row = g_xh2 + (size_t)warp * C2;
    float s = 0.f, d = 0.f;
    for (int c = lane; c < C2; c += 32) {
        float v = row[c];
        s += v * a_src[c];
        d += v * a_dst[c];
    }
#pragma unroll
    for (int o = 16; o; o >>= 1) {
        s += __shfl_down_sync(0xffffffffu, s, o);
        d += __shfl_down_sync(0xffffffffu, d, o);
    }
    if (lane == 0) { g_als2[warp] = s; g_ald2[warp] = d; }
}

// per-edge w = exp(leaky_relu(als[src]+ald[dst])); accumulate z[dst].
// No max-subtraction: alpha = e^x / sum e^x is shift-invariant and |x| is small.
__global__ void edge_w1_kernel(const int* __restrict__ ei) {
    int e = blockIdx.x * blockDim.x + threadIdx.x;
    if (e >= NET) return;
    int s, d;
    if (e < NE) { s = ei[e]; d = ei[NE + e]; }
    else        { s = d = e - NE; }
#pragma unroll
    for (int h = 0; h < H1; h++) {
        float v = g_als1[s * H1 + h] + g_ald1[d * H1 + h];
        v = (v > 0.f) ? v : NEG_SLOPE * v;
        float w = __expf(v);
        g_ew1[(size_t)e * H1 + h] = w;
        atomicAdd(&g_z1[d * H1 + h], w);
    }
}

__global__ void edge_w2_kernel(const int* __restrict__ ei) {
    int e = blockIdx.x * blockDim.x + threadIdx.x;
    if (e >= NET) return;
    int s, d;
    if (e < NE) { s = ei[e]; d = ei[NE + e]; }
    else        { s = d = e - NE; }
    float v = g_als2[s] + g_ald2[d];
    v = (v > 0.f) ? v : NEG_SLOPE * v;
    float w = __expf(v);
    g_ew2[e] = w;
    atomicAdd(&g_z2[d], w);
}

// warp-per-edge scatter: h1[dst, :] += alpha_h * xh1[src, :]   (128 channels, 2 heads)
__global__ void edge_agg1_kernel(const int* __restrict__ ei) {
    int warp = (blockIdx.x * blockDim.x + threadIdx.x) >> 5;
    int lane = threadIdx.x & 31;
    if (warp >= NET) return;
    int s, d;
    if (warp < NE) { s = ei[warp]; d = ei[NE + warp]; }
    else           { s = d = warp - NE; }
    float alpha0 = g_ew1[(size_t)warp * H1]     / g_z1[d * H1];
    float alpha1 = g_ew1[(size_t)warp * H1 + 1] / g_z1[d * H1 + 1];
    const float* src_row = g_xh1 + (size_t)s * HC1;
    float* dst_row = g_h1 + (size_t)d * HC1;
#pragma unroll
    for (int k = 0; k < 4; k++) {
        int c = k * 32 + lane;
        float a = (c < C1) ? alpha0 : alpha1;
        atomicAdd(&dst_row[c], a * src_row[c]);
    }
}

// warp-per-edge scatter: h2[dst, :] += alpha * xh2[src, :]   (64 channels)
__global__ void edge_agg2_kernel(const int* __restrict__ ei) {
    int warp = (blockIdx.x * blockDim.x + threadIdx.x) >> 5;
    int lane = threadIdx.x & 31;
    if (warp >= NET) return;
    int s, d;
    if (warp < NE) { s = ei[warp]; d = ei[NE + warp]; }
    else           { s = d = warp - NE; }
    float alpha = g_ew2[warp] / g_z2[d];
    const float* src_row = g_xh2 + (size_t)s * HC2;
    float* dst_row = g_h2 + (size_t)d * HC2;
#pragma unroll
    for (int k = 0; k < 2; k++) {
        int c = k * 32 + lane;
        atomicAdd(&dst_row[c], alpha * src_row[c]);
    }
}

__global__ void bias_relu1_kernel(const float* __restrict__ b) {
    int i = blockIdx.x * blockDim.x + threadIdx.x;
    if (i >= NN * HC1) return;
    float v = g_h1[i] + b[i & (HC1 - 1)];
    g_h1[i] = fmaxf(v, 0.0f);
}

__global__ void bias2_kernel(const float* __restrict__ b) {
    int i = blockIdx.x * blockDim.x + threadIdx.x;
    if (i >= NN * HC2) return;
    g_h2[i] = g_h2[i] + b[i & (HC2 - 1)];
}

__global__ void pool_zero_kernel(float* __restrict__ out) {
    int i = blockIdx.x * blockDim.x + threadIdx.x;
    if (i < NG * HC2) out[i] = 0.0f;
}

__global__ void pool_kernel(const int* __restrict__ batch, float* __restrict__ ge) {
    int i = blockIdx.x * blockDim.x + threadIdx.x;
    if (i >= NN * HC2) return;
    int n = i >> 6, c = i & 63;
    atomicAdd(&ge[batch[n] * HC2 + c], g_h2[i]);
}

// single block, 64 threads: MLP head + log-softmax + loss + correct count
__global__ void classifier_kernel(const float* __restrict__ Wc1, const float* __restrict__ bc1,
                                  const float* __restrict__ Wc2, const float* __restrict__ bc2,
                                  const int* __restrict__ y,
                                  float* __restrict__ out) {
    int g = threadIdx.x;  // 0..63
    const float* ge = out;  // graph embedding at out[0..NG*HC2)
    __shared__ float loss_sh[NG];
    __shared__ int corr_sh[NG];
    float l0 = bc2[0], l1 = bc2[1];
    for (int j = 0; j < CLSH; j++) {
        float h = bc1[j];
        for (int k = 0; k < HC2; k++) h += ge[g * HC2 + k] * Wc1[k * CLSH + j];
        h = fmaxf(h, 0.0f);
        l0 += h * Wc2[j * 2];
        l1 += h * Wc2[j * 2 + 1];
    }
    float m = fmaxf(l0, l1);
    float e0 = expf(l0 - m), e1 = expf(l1 - m);
    float lse = m + logf(e0 + e1);
    float lp0 = l0 - lse, lp1 = l1 - lse;
    float p0 = expf(lp0), p1 = expf(lp1);
    int yv = y[g];
    loss_sh[g] = -((yv == 0) ? lp0 : lp1);
    corr_sh[g] = (((p1 > p0) ? 1 : 0) == yv) ? 1 : 0;
    out[NG * HC2 + 2 + g * 2]     = p0;
    out[NG * HC2 + 2 + g * 2 + 1] = p1;
    __syncthreads();
    if (g == 0) {
        float L = 0.f; int cc = 0;
        for (int i = 0; i < NG; i++) { L += loss_sh[i]; cc += corr_sh[i]; }
        out[NG * HC2]     = L / (float)NG;
        out[NG * HC2 + 1] = (float)cc;
    }
}

// ---------------- launch ----------------
static inline int cdiv(int a, int b) { return (a + b - 1) / b; }

extern "C" void kernel_launch(void* const* d_in, const int* in_sizes, int n_in,
                              void* d_out, int out_size) {
    const float* x     = (const float*)d_in[0];
    const int*   ei    = (const int*)d_in[1];     // int32 (JAX x64 disabled)
    const int*   batch = (const int*)d_in[2];
    const int*   y     = (const int*)d_in[3];
    const float* W1    = (const float*)d_in[4];
    const float* asrc1 = (const float*)d_in[5];
    const float* adst1 = (const float*)d_in[6];
    const float* b1    = (const float*)d_in[7];
    const float* W2    = (const float*)d_in[8];
    const float* asrc2 = (const float*)d_in[9];
    const float* adst2 = (const float*)d_in[10];
    const float* b2    = (const float*)d_in[11];
    const float* Wc1   = (const float*)d_in[12];
    const float* bc1   = (const float*)d_in[13];
    const float* Wc2   = (const float*)d_in[14];
    const float* bc2   = (const float*)d_in[15];
    float* out = (float*)d_out;

    dim3 t16(16, 16);

    zero_scratch_kernel<<<cdiv(NN * HC1, 256), 256>>>();

    // ---- layer 1 ----
    gemm1_kernel<<<dim3(HC1 / 64, cdiv(NN, 64)), t16>>>(x, W1);
    al1_kernel<<<cdiv(NN * H1 * 32, 256), 256>>>(asrc1, adst1);
    edge_w1_kernel<<<cdiv(NET, 256), 256>>>(ei);
    edge_agg1_kernel<<<cdiv(NET * 32, 256), 256>>>(ei);
    bias_relu1_kernel<<<cdiv(NN * HC1, 256), 256>>>(b1);

    // ---- layer 2 ----
    gemm2_kernel<<<dim3(HC2 / 64, cdiv(NN, 64)), t16>>>(W2);
    al2_kernel<<<cdiv(NN * 32, 256), 256>>>(asrc2, adst2);
    edge_w2_kernel<<<cdiv(NET, 256), 256>>>(ei);
    edge_agg2_kernel<<<cdiv(NET * 32, 256), 256>>>(ei);
    bias2_kernel<<<cdiv(NN * HC2, 256), 256>>>(b2);

    // ---- pool + classifier ----
    pool_zero_kernel<<<cdiv(NG * HC2, 256), 256>>>(out);
    pool_kernel<<<cdiv(NN * HC2, 256), 256>>>(batch, out);
    classifier_kernel<<<1, NG>>>(Wc1, bc1, Wc2, bc2, y, out);
}

// round 13
// speedup vs baseline: 1.0041x; 1.0012x over previous
#include <cuda_runtime.h>
#include <cuda_bf16.h>
#include <math.h>

// ---------------- problem constants ----------------
#define NN 20000          // nodes
#define NE 640000         // edges (before self-loops)
#define NET (NE + NN)     // edges with self-loops
#define NG 64             // graphs
#define FIN 128
#define C1 64             // per-head channels layer1 (2 heads -> 128)
#define H1 2
#define HC1 (H1 * C1)     // 128
#define C2 64
#define HC2 64
#define CLSH 64
#define NEG_SLOPE 0.2f

// ---------------- device scratch (referenced directly by symbol in kernels) ----------------
__device__ float g_xh1[NN * HC1];
__device__ float g_h1[NN * HC1];
__device__ float g_xh2[NN * HC2];
__device__ float g_h2[NN * HC2];
__device__ float g_als1[NN * H1];
__device__ float g_ald1[NN * H1];
__device__ float g_z1[NN * H1];
__device__ float g_als2[NN];
__device__ float g_ald2[NN];
__device__ float g_z2[NN];
__device__ float g_ew1[(size_t)NET * H1];
__device__ float g_ew2[(size_t)NET];

// ---------------- kernels ----------------

// zero all per-call accumulators (z1, z2, h1, h2) in one kernel
__global__ void zero_scratch_kernel() {
    int i = blockIdx.x * blockDim.x + threadIdx.x;
    if (i < NN * HC1) g_h1[i] = 0.0f;
    if (i < NN * HC2) g_h2[i] = 0.0f;
    if (i < NN * H1)  g_z1[i] = 0.0f;
    if (i < NN)       g_z2[i] = 0.0f;
}

// C[M,N] = A[M,K] @ B[K,N].  BM=BN=64, BK=16, 16x16 threads, 4x4 per thread.
__device__ __forceinline__ void gemm_body(const float* __restrict__ A, const float* __restrict__ B,
                                          float* __restrict__ C, int M, int N, int K) {
    __shared__ float As[64][17];
    __shared__ float Bs[16][64];
    int block_row = blockIdx.y * 64;
    int block_col = blockIdx.x * 64;
    int tx = threadIdx.x, ty = threadIdx.y;
    int tid = ty * 16 + tx;
    float acc[4][4] = {};
    for (int k0 = 0; k0 < K; k0 += 16) {
        for (int i = tid; i < 64 * 16; i += 256) {
            int r = i >> 4, c = i & 15;
            int gr = block_row + r;
            As[r][c] = (gr < M) ? A[(size_t)gr * K + k0 + c] : 0.0f;
        }
        for (int i = tid; i < 16 * 64; i += 256) {
            int r = i >> 6, c = i & 63;
            Bs[r][c] = B[(size_t)(k0 + r) * N + block_col + c];
        }
        __syncthreads();
#pragma unroll
        for (int kk = 0; kk < 16; kk++) {
            float a[4], b[4];
#pragma unroll
            for (int i = 0; i < 4; i++) a[i] = As[ty * 4 + i][kk];
#pragma unroll
            for (int j = 0; j < 4; j++) b[j] = Bs[kk][tx * 4 + j];
#pragma unroll
            for (int i = 0; i < 4; i++)
#pragma unroll
                for (int j = 0; j < 4; j++) acc[i][j] += a[i] * b[j];
        }
        __syncthreads();
    }
#pragma unroll
    for (int i = 0; i < 4; i++) {
        int gr = block_row + ty * 4 + i;
        if (gr < M) {
#pragma unroll
            for (int j = 0; j < 4; j++)
                C[(size_t)gr * N + block_col + tx * 4 + j] = acc[i][j];
        }
    }
}

__global__ void gemm1_kernel(const float* __restrict__ A, const float* __restrict__ B) {
    gemm_body(A, B, g_xh1, NN, HC1, FIN);
}
__global__ void gemm2_kernel(const float* __restrict__ B) {
    gemm_body(g_h1, B, g_xh2, NN, HC2, HC1);
}

// per-(node,head) attention logit halves
__global__ void al1_kernel(const float* __restrict__ a_src, const float* __restrict__ a_dst) {
    int warp = (blockIdx.x * blockDim.x + threadIdx.x) >> 5;  // warp = n*H1 + h
    int lane = threadIdx.x & 31;
    if (warp >= NN * H1) return;
    int h = warp & 1;
    const float* row = g_xh1 + (size_t)warp * C1;
    float s = 0.f, d = 0.f;
    for (int c = lane; c < C1; c += 32) {
        float v = row[c];
        s += v * a_src[h * C1 + c];
        d += v * a_dst[h * C1 + c];
    }
#pragma unroll
    for (int o = 16; o; o >>= 1) {
        s += __shfl_down_sync(0xffffffffu, s, o);
        d += __shfl_down_sync(0xffffffffu, d, o);
    }
    if (lane == 0) { g_als1[warp] = s; g_ald1[warp] = d; }
}

__global__ void al2_kernel(const float* __restrict__ a_src, const float* __restrict__ a_dst) {
    int warp = (blockIdx.x * blockDim.x + threadIdx.x) >> 5;
    int lane = threadIdx.x & 31;
    if (warp >= NN) return;
    const float* row = g_xh2 + (size_t)warp * C2;
    float s = 0.f, d = 0.f;
    for (int c = lane; c < C2; c += 32) {
        float v = row[c];
        s += v * a_src[c];
        d += v * a_dst[c];
    }
#pragma unroll
    for (int o = 16; o; o >>= 1) {
        s += __shfl_down_sync(0xffffffffu, s, o);
        d += __shfl_down_sync(0xffffffffu, d, o);
    }
    if (lane == 0) { g_als2[warp] = s; g_ald2[warp] = d; }
}

// per-edge w = exp(leaky_relu(als[src]+ald[dst])); accumulate z[dst].
// No max-subtraction: alpha = e^x / sum e^x is shift-invariant and |x| is small.
__global__ void edge_w1_kernel(const int* __restrict__ ei) {
    int e = blockIdx.x * blockDim.x + threadIdx.x;
    if (e >= NET) return;
    int s, d;
    if (e < NE) { s = ei[e]; d = ei[NE + e]; }
    else        { s = d = e - NE; }
#pragma unroll
    for (int h = 0; h < H1; h++) {
        float v = g_als1[s * H1 + h] + g_ald1[d * H1 + h];
        v = (v > 0.f) ? v : NEG_SLOPE * v;
        float w = __expf(v);
        g_ew1[(size_t)e * H1 + h] = w;
        atomicAdd(&g_z1[d * H1 + h], w);
    }
}

__global__ void edge_w2_kernel(const int* __restrict__ ei) {
    int e = blockIdx.x * blockDim.x + threadIdx.x;
    if (e >= NET) return;
    int s, d;
    if (e < NE) { s = ei[e]; d = ei[NE + e]; }
    else        { s = d = e - NE; }
    float v = g_als2[s] + g_ald2[d];
    v = (v > 0.f) ? v : NEG_SLOPE * v;
    float w = __expf(v);
    g_ew2[e] = w;
    atomicAdd(&g_z2[d], w);
}

// warp-per-edge scatter: h1[dst, :] += alpha_h * xh1[src, :]   (128 channels, 2 heads)
__global__ void edge_agg1_kernel(const int* __restrict__ ei) {
    int warp = (blockIdx.x * blockDim.x + threadIdx.x) >> 5;
    int lane = threadIdx.x & 31;
    if (warp >= NET) return;
    int s, d;
    if (warp < NE) { s = ei[warp]; d = ei[NE + warp]; }
    else           { s = d = warp - NE; }
    float alpha0 = g_ew1[(size_t)warp * H1]     / g_z1[d * H1];
    float alpha1 = g_ew1[(size_t)warp * H1 + 1] / g_z1[d * H1 + 1];
    const float* src_row = g_xh1 + (size_t)s * HC1;
    float* dst_row = g_h1 + (size_t)d * HC1;
#pragma unroll
    for (int k = 0; k < 4; k++) {
        int c = k * 32 + lane;
        float a = (c < C1) ? alpha0 : alpha1;
        atomicAdd(&dst_row[c], a * src_row[c]);
    }
}

// warp-per-edge scatter: h2[dst, :] += alpha * xh2[src, :]   (64 channels)
__global__ void edge_agg2_kernel(const int* __restrict__ ei) {
    int warp = (blockIdx.x * blockDim.x + threadIdx.x) >> 5;
    int lane = threadIdx.x & 31;
    if (warp >= NET) return;
    int s, d;
    if (warp < NE) { s = ei[warp]; d = ei[NE + warp]; }
    else           { s = d = warp - NE; }
    float alpha = g_ew2[warp] / g_z2[d];
    const float* src_row = g_xh2 + (size_t)s * HC2;
    float* dst_row = g_h2 + (size_t)d * HC2;
#pragma unroll
    for (int k = 0; k < 2; k++) {
        int c = k * 32 + lane;
        atomicAdd(&dst_row[c], alpha * src_row[c]);
    }
}

__global__ void bias_relu1_kernel(const float* __restrict__ b) {
    int i = blockIdx.x * blockDim.x + threadIdx.x;
    if (i >= NN * HC1) return;
    float v = g_h1[i] + b[i & (HC1 - 1)];
    g_h1[i] = fmaxf(v, 0.0f);
}

__global__ void bias2_kernel(const float* __restrict__ b) {
    int i = blockIdx.x * blockDim.x + threadIdx.x;
    if (i >= NN * HC2) return;
    g_h2[i] = g_h2[i] + b[i & (HC2 - 1)];
}

__global__ void pool_zero_kernel(float* __restrict__ out) {
    int i = blockIdx.x * blockDim.x + threadIdx.x;
    if (i < NG * HC2) out[i] = 0.0f;
}

__global__ void pool_kernel(const int* __restrict__ batch, float* __restrict__ ge) {
    int i = blockIdx.x * blockDim.x + threadIdx.x;
    if (i >= NN * HC2) return;
    int n = i >> 6, c = i & 63;
    atomicAdd(&ge[batch[n] * HC2 + c], g_h2[i]);
}

// single block, 64 threads: MLP head + log-softmax + loss + correct count
__global__ void classifier_kernel(const float* __restrict__ Wc1, const float* __restrict__ bc1,
                                  const float* __restrict__ Wc2, const float* __restrict__ bc2,
                                  const int* __restrict__ y,
                                  float* __restrict__ out) {
    int g = threadIdx.x;  // 0..63
    const float* ge = out;  // graph embedding at out[0..NG*HC2)
    __shared__ float loss_sh[NG];
    __shared__ int corr_sh[NG];
    float l0 = bc2[0], l1 = bc2[1];
    for (int j = 0; j < CLSH; j++) {
        float h = bc1[j];
        for (int k = 0; k < HC2; k++) h += ge[g * HC2 + k] * Wc1[k * CLSH + j];
        h = fmaxf(h, 0.0f);
        l0 += h * Wc2[j * 2];
        l1 += h * Wc2[j * 2 + 1];
    }
    float m = fmaxf(l0, l1);
    float e0 = expf(l0 - m), e1 = expf(l1 - m);
    float lse = m + logf(e0 + e1);
    float lp0 = l0 - lse, lp1 = l1 - lse;
    float p0 = expf(lp0), p1 = expf(lp1);
    int yv = y[g];
    loss_sh[g] = -((yv == 0) ? lp0 : lp1);
    corr_sh[g] = (((p1 > p0) ? 1 : 0) == yv) ? 1 : 0;
    out[NG * HC2 + 2 + g * 2]     = p0;
    out[NG * HC2 + 2 + g * 2 + 1] = p1;
    __syncthreads();
    if (g == 0) {
        float L = 0.f; int cc = 0;
        for (int i = 0; i < NG; i++) { L += loss_sh[i]; cc += corr_sh[i]; }
        out[NG * HC2]     = L / (float)NG;
        out[NG * HC2 + 1] = (float)cc;
    }
}

// ---------------- launch ----------------
static inline int cdiv(int a, int b) { return (a + b - 1) / b; }

extern "C" void kernel_launch(void* const* d_in, const int* in_sizes, int n_in,
                              void* d_out, int out_size) {
    const float* x     = (const float*)d_in[0];
    const int*   ei    = (const int*)d_in[1];     // int32 (JAX x64 disabled)
    const int*   batch = (const int*)d_in[2];
    const int*   y     = (const int*)d_in[3];
    const float* W1    = (const float*)d_in[4];
    const float* asrc1 = (const float*)d_in[5];
    const float* adst1 = (const float*)d_in[6];
    const float* b1    = (const float*)d_in[7];
    const float* W2    = (const float*)d_in[8];
    const float* asrc2 = (const float*)d_in[9];
    const float* adst2 = (const float*)d_in[10];
    const float* b2    = (const float*)d_in[11];
    const float* Wc1   = (const float*)d_in[12];
    const float* bc1   = (const float*)d_in[13];
    const float* Wc2   = (const float*)d_in[14];
    const float* bc2   = (const float*)d_in[15];
    float* out = (float*)d_out;

    dim3 t16(16, 16);

    zero_scratch_kernel<<<cdiv(NN * HC1, 256), 256>>>();

    // ---- layer 1 ----
    gemm1_kernel<<<dim3(HC1 / 64, cdiv(NN, 64)), t16>>>(x, W1);
    al1_kernel<<<cdiv(NN * H1 * 32, 256), 256>>>(asrc1, adst1);
    edge_w1_kernel<<<cdiv(NET, 256), 256>>>(ei);
    edge_agg1_kernel<<<cdiv(NET * 32, 256), 256>>>(ei);
    bias_relu1_kernel<<<cdiv(NN * HC1, 256), 256>>>(b1);

    // ---- layer 2 ----
    gemm2_kernel<<<dim3(HC2 / 64, cdiv(NN, 64)), t16>>>(W2);
    al2_kernel<<<cdiv(NN * 32, 256), 256>>>(asrc2, adst2);
    edge_w2_kernel<<<cdiv(NET, 256), 256>>>(ei);
    edge_agg2_kernel<<<cdiv(NET * 32, 256), 256>>>(ei);
    bias2_kernel<<<cdiv(NN * HC2, 256), 256>>>(b2);

    // ---- pool + classifier ----
    pool_zero_kernel<<<cdiv(NG * HC2, 256), 256>>>(out);
    pool_kernel<<<cdiv(NN * HC2, 256), 256>>>(batch, out);
    classifier_kernel<<<1, NG>>>(Wc1, bc1, Wc2, bc2, y, out);
}

// round 14
// speedup vs baseline: 1.0100x; 1.0059x over previous
#include <cuda_runtime.h>
#include <cuda_bf16.h>
#include <math.h>

// ---------------- problem constants ----------------
#define NN 20000          // nodes
#define NE 640000         // edges (before self-loops)
#define NET (NE + NN)     // edges with self-loops
#define NG 64             // graphs
#define FIN 128
#define C1 64             // per-head channels layer1 (2 heads -> 128)
#define H1 2
#define HC1 (H1 * C1)     // 128
#define C2 64
#define HC2 64
#define CLSH 64
#define NEG_SLOPE 0.2f

// ---------------- device scratch (referenced directly by symbol in kernels) ----------------
__device__ float g_xh1[NN * HC1];
__device__ float g_h1[NN * HC1];
__device__ float g_xh2[NN * HC2];
__device__ float g_h2[NN * HC2];
__device__ float g_als1[NN * H1];
__device__ float g_ald1[NN * H1];
__device__ float g_z1[NN * H1];
__device__ float g_als2[NN];
__device__ float g_ald2[NN];
__device__ float g_z2[NN];
__device__ float g_ew1[(size_t)NET * H1];
__device__ float g_ew2[(size_t)NET];

// ---------------- kernels ----------------

// zero all per-call accumulators (z1, z2, h1, h2) in one kernel
__global__ void zero_scratch_kernel() {
    int i = blockIdx.x * blockDim.x + threadIdx.x;
    if (i < NN * HC1) g_h1[i] = 0.0f;
    if (i < NN * HC2) g_h2[i] = 0.0f;
    if (i < NN * H1)  g_z1[i] = 0.0f;
    if (i < NN)       g_z2[i] = 0.0f;
}

// C[M,N] = A[M,K] @ B[K,N].  BM=BN=64, BK=16, 16x16 threads, 4x4 per thread.
__device__ __forceinline__ void gemm_body(const float* __restrict__ A, const float* __restrict__ B,
                                          float* __restrict__ C, int M, int N, int K) {
    __shared__ float As[64][17];
    __shared__ float Bs[16][64];
    int block_row = blockIdx.y * 64;
    int block_col = blockIdx.x * 64;
    int tx = threadIdx.x, ty = threadIdx.y;
    int tid = ty * 16 + tx;
    float acc[4][4] = {};
    for (int k0 = 0; k0 < K; k0 += 16) {
        for (int i = tid; i < 64 * 16; i += 256) {
            int r = i >> 4, c = i & 15;
            int gr = block_row + r;
            As[r][c] = (gr < M) ? A[(size_t)gr * K + k0 + c] : 0.0f;
        }
        for (int i = tid; i < 16 * 64; i += 256) {
            int r = i >> 6, c = i & 63;
            Bs[r][c] = B[(size_t)(k0 + r) * N + block_col + c];
        }
        __syncthreads();
#pragma unroll
        for (int kk = 0; kk < 16; kk++) {
            float a[4], b[4];
#pragma unroll
            for (int i = 0; i < 4; i++) a[i] = As[ty * 4 + i][kk];
#pragma unroll
            for (int j = 0; j < 4; j++) b[j] = Bs[kk][tx * 4 + j];
#pragma unroll
            for (int i = 0; i < 4; i++)
#pragma unroll
                for (int j = 0; j < 4; j++) acc[i][j] += a[i] * b[j];
        }
        __syncthreads();
    }
#pragma unroll
    for (int i = 0; i < 4; i++) {
        int gr = block_row + ty * 4 + i;
        if (gr < M) {
#pragma unroll
            for (int j = 0; j < 4; j++)
                C[(size_t)gr * N + block_col + tx * 4 + j] = acc[i][j];
        }
    }
}

__global__ void gemm1_kernel(const float* __restrict__ A, const float* __restrict__ B) {
    gemm_body(A, B, g_xh1, NN, HC1, FIN);
}
__global__ void gemm2_kernel(const float* __restrict__ B) {
    gemm_body(g_h1, B, g_xh2, NN, HC2, HC1);
}

// per-(node,head) attention logit halves
__global__ void al1_kernel(const float* __restrict__ a_src, const float* __restrict__ a_dst) {
    int warp = (blockIdx.x * blockDim.x + threadIdx.x) >> 5;  // warp = n*H1 + h
    int lane = threadIdx.x & 31;
    if (warp >= NN * H1) return;
    int h = warp & 1;
    const float* row = g_xh1 + (size_t)warp * C1;
    float s = 0.f, d = 0.f;
    for (int c = lane; c < C1; c += 32) {
        float v = row[c];
        s += v * a_src[h * C1 + c];
        d += v * a_dst[h * C1 + c];
    }
#pragma unroll
    for (int o = 16; o; o >>= 1) {
        s += __shfl_down_sync(0xffffffffu, s, o);
        d += __shfl_down_sync(0xffffffffu, d, o);
    }
    if (lane == 0) { g_als1[warp] = s; g_ald1[warp] = d; }
}

__global__ void al2_kernel(const float* __restrict__ a_src, const float* __restrict__ a_dst) {
    int warp = (blockIdx.x * blockDim.x + threadIdx.x) >> 5;
    int lane = threadIdx.x & 31;
    if (warp >= NN) return;
    const float* row = g_xh2 + (size_t)warp * C2;
    float s = 0.f, d = 0.f;
    for (int c = lane; c < C2; c += 32) {
        float v = row[c];
        s += v * a_src[c];
        d += v * a_dst[c];
    }
#pragma unroll
    for (int o = 16; o; o >>= 1) {
        s += __shfl_down_sync(0xffffffffu, s, o);
        d += __shfl_down_sync(0xffffffffu, d, o);
    }
    if (lane == 0) { g_als2[warp] = s; g_ald2[warp] = d; }
}

// per-edge w = exp(leaky_relu(als[src]+ald[dst])); accumulate z[dst].
// No max-subtraction: alpha = e^x / sum e^x is shift-invariant and |x| is small.
__global__ void edge_w1_kernel(const int* __restrict__ ei) {
    int e = blockIdx.x * blockDim.x + threadIdx.x;
    if (e >= NET) return;
    int s, d;
    if (e < NE) { s = ei[e]; d = ei[NE + e]; }
    else        { s = d = e - NE; }
#pragma unroll
    for (int h = 0; h < H1; h++) {
        float v = g_als1[s * H1 + h] + g_ald1[d * H1 + h];
        v = (v > 0.f) ? v : NEG_SLOPE * v;
        float w = __expf(v);
        g_ew1[(size_t)e * H1 + h] = w;
        atomicAdd(&g_z1[d * H1 + h], w);
    }
}

__global__ void edge_w2_kernel(const int* __restrict__ ei) {
    int e = blockIdx.x * blockDim.x + threadIdx.x;
    if (e >= NET) return;
    int s, d;
    if (e < NE) { s = ei[e]; d = ei[NE + e]; }
    else        { s = d = e - NE; }
    float v = g_als2[s] + g_ald2[d];
    v = (v > 0.f) ? v : NEG_SLOPE * v;
    float w = __expf(v);
    g_ew2[e] = w;
    atomicAdd(&g_z2[d], w);
}

// warp-per-edge scatter: h1[dst, :] += alpha_h * xh1[src, :]   (128 channels, 2 heads)
__global__ void edge_agg1_kernel(const int* __restrict__ ei) {
    int warp = (blockIdx.x * blockDim.x + threadIdx.x) >> 5;
    int lane = threadIdx.x & 31;
    if (warp >= NET) return;
    int s, d;
    if (warp < NE) { s = ei[warp]; d = ei[NE + warp]; }
    else           { s = d = warp - NE; }
    float alpha0 = g_ew1[(size_t)warp * H1]     / g_z1[d * H1];
    float alpha1 = g_ew1[(size_t)warp * H1 + 1] / g_z1[d * H1 + 1];
    const float* src_row = g_xh1 + (size_t)s * HC1;
    float* dst_row = g_h1 + (size_t)d * HC1;
#pragma unroll
    for (int k = 0; k < 4; k++) {
        int c = k * 32 + lane;
        float a = (c < C1) ? alpha0 : alpha1;
        atomicAdd(&dst_row[c], a * src_row[c]);
    }
}

// warp-per-edge scatter: h2[dst, :] += alpha * xh2[src, :]   (64 channels)
__global__ void edge_agg2_kernel(const int* __restrict__ ei) {
    int warp = (blockIdx.x * blockDim.x + threadIdx.x) >> 5;
    int lane = threadIdx.x & 31;
    if (warp >= NET) return;
    int s, d;
    if (warp < NE) { s = ei[warp]; d = ei[NE + warp]; }
    else           { s = d = warp - NE; }
    float alpha = g_ew2[warp] / g_z2[d];
    const float* src_row = g_xh2 + (size_t)s * HC2;
    float* dst_row = g_h2 + (size_t)d * HC2;
#pragma unroll
    for (int k = 0; k < 2; k++) {
        int c = k * 32 + lane;
        atomicAdd(&dst_row[c], alpha * src_row[c]);
    }
}

__global__ void bias_relu1_kernel(const float* __restrict__ b) {
    int i = blockIdx.x * blockDim.x + threadIdx.x;
    if (i >= NN * HC1) return;
    float v = g_h1[i] + b[i & (HC1 - 1)];
    g_h1[i] = fmaxf(v, 0.0f);
}

__global__ void bias2_kernel(const float* __restrict__ b) {
    int i = blockIdx.x * blockDim.x + threadIdx.x;
    if (i >= NN * HC2) return;
    g_h2[i] = g_h2[i] + b[i & (HC2 - 1)];
}

__global__ void pool_zero_kernel(float* __restrict__ out) {
    int i = blockIdx.x * blockDim.x + threadIdx.x;
    if (i < NG * HC2) out[i] = 0.0f;
}

__global__ void pool_kernel(const int* __restrict__ batch, float* __restrict__ ge) {
    int i = blockIdx.x * blockDim.x + threadIdx.x;
    if (i >= NN * HC2) return;
    int n = i >> 6, c = i & 63;
    atomicAdd(&ge[batch[n] * HC2 + c], g_h2[i]);
}

// single block, 64 threads: MLP head + log-softmax + loss + correct count
__global__ void classifier_kernel(const float* __restrict__ Wc1, const float* __restrict__ bc1,
                                  const float* __restrict__ Wc2, const float* __restrict__ bc2,
                                  const int* __restrict__ y,
                                  float* __restrict__ out) {
    int g = threadIdx.x;  // 0..63
    const float* ge = out;  // graph embedding at out[0..NG*HC2)
    __shared__ float loss_sh[NG];
    __shared__ int corr_sh[NG];
    float l0 = bc2[0], l1 = bc2[1];
    for (int j = 0; j < CLSH; j++) {
        float h = bc1[j];
        for (int k = 0; k < HC2; k++) h += ge[g * HC2 + k] * Wc1[k * CLSH + j];
        h = fmaxf(h, 0.0f);
        l0 += h * Wc2[j * 2];
        l1 += h * Wc2[j * 2 + 1];
    }
    float m = fmaxf(l0, l1);
    float e0 = expf(l0 - m), e1 = expf(l1 - m);
    float lse = m + logf(e0 + e1);
    float lp0 = l0 - lse, lp1 = l1 - lse;
    float p0 = expf(lp0), p1 = expf(lp1);
    int yv = y[g];
    loss_sh[g] = -((yv == 0) ? lp0 : lp1);
    corr_sh[g] = (((p1 > p0) ? 1 : 0) == yv) ? 1 : 0;
    out[NG * HC2 + 2 + g * 2]     = p0;
    out[NG * HC2 + 2 + g * 2 + 1] = p1;
    __syncthreads();
    if (g == 0) {
        float L = 0.f; int cc = 0;
        for (int i = 0; i < NG; i++) { L += loss_sh[i]; cc += corr_sh[i]; }
        out[NG * HC2]     = L / (float)NG;
        out[NG * HC2 + 1] = (float)cc;
    }
}

// ---------------- launch ----------------
static inline int cdiv(int a, int b) { return (a + b - 1) / b; }

extern "C" void kernel_launch(void* const* d_in, const int* in_sizes, int n_in,
                              void* d_out, int out_size) {
    const float* x     = (const float*)d_in[0];
    const int*   ei    = (const int*)d_in[1];     // int32 (JAX x64 disabled)
    const int*   batch = (const int*)d_in[2];
    const int*   y     = (const int*)d_in[3];
    const float* W1    = (const float*)d_in[4];
    const float* asrc1 = (const float*)d_in[5];
    const float* adst1 = (const float*)d_in[6];
    const float* b1    = (const float*)d_in[7];
    const float* W2    = (const float*)d_in[8];
    const float* asrc2 = (const float*)d_in[9];
    const float* adst2 = (const float*)d_in[10];
    const float* b2    = (const float*)d_in[11];
    const float* Wc1   = (const float*)d_in[12];
    const float* bc1   = (const float*)d_in[13];
    const float* Wc2   = (const float*)d_in[14];
    const float* bc2   = (const float*)d_in[15];
    float* out = (float*)d_out;

    dim3 t16(16, 16);

    zero_scratch_kernel<<<cdiv(NN * HC1, 256), 256>>>();

    // ---- layer 1 ----
    gemm1_kernel<<<dim3(HC1 / 64, cdiv(NN, 64)), t16>>>(x, W1);
    al1_kernel<<<cdiv(NN * H1 * 32, 256), 256>>>(asrc1, adst1);
    edge_w1_kernel<<<cdiv(NET, 256), 256>>>(ei);
    edge_agg1_kernel<<<cdiv(NET * 32, 256), 256>>>(ei);
    bias_relu1_kernel<<<cdiv(NN * HC1, 256), 256>>>(b1);

    // ---- layer 2 ----
    gemm2_kernel<<<dim3(HC2 / 64, cdiv(NN, 64)), t16>>>(W2);
    al2_kernel<<<cdiv(NN * 32, 256), 256>>>(asrc2, adst2);
    edge_w2_kernel<<<cdiv(NET, 256), 256>>>(ei);
    edge_agg2_kernel<<<cdiv(NET * 32, 256), 256>>>(ei);
    bias2_kernel<<<cdiv(NN * HC2, 256), 256>>>(b2);

    // ---- pool + classifier ----
    pool_zero_kernel<<<cdiv(NG * HC2, 256), 256>>>(out);
    pool_kernel<<<cdiv(NN * HC2, 256), 256>>>(batch, out);
    classifier_kernel<<<1, NG>>>(Wc1, bc1, Wc2, bc2, y, out);
}